// round 15
// baseline (speedup 1.0000x reference)
#include <cuda_runtime.h>

#define TT     32768
#define HID    100
#define DIN    300
#define THR    200                 // uniform block size
#define XROW   400                 // xp row stride (floats)
#define XROW2  200                 // xp row stride (float2)
#define XTILE  32                  // xp0 producer tile (timesteps)
#define NXTILE (TT / XTILE)        // 1024
#define NXPB   64                  // xp0 producer blocks
#define CH     64                  // chaser chunk (timesteps)
#define NCHUNK (TT / CH)           // 512
#define NCHASE 8
#define OT     16                  // out_gemm tile (timesteps)

// ---------------- scratch (static device allocations) ----------------------
// xp rows pre-scaled: i,f,o rows x0.5 (sigmoid via 0.5+0.5*tanh(y)), g rows x1
__device__ float g_xp0[(TT + 2) * XROW];  // layer-0 input proj, [t][4u+{i,g,f,o}]
__device__ float g_xp1[(TT + 2) * XROW];  // layer-1 input proj, same layout
__device__ float g_h0[TT * HID];          // layer-0 hidden sequence [t][u]
__device__ float g_h1[TT * HID];          // layer-1 hidden sequence [t][u]
__device__ float g_WcT[DIN * 400];        // fused (W_ih_l0 @ W_inp)^T [k][j], row-scaled
__device__ float g_bc[400];               // fused layer-0 gate bias, row-scaled
__device__ float g_WoutT[HID * DIN];      // W_out transposed [k][d]
__device__ volatile int g_prog0;          // layer-0 progress (steps completed)
__device__ volatile int g_flag0[NXTILE];  // xp0 tile-ready flags
__device__ volatile int g_flag1[NCHUNK];  // xp1 chunk-ready flags

typedef unsigned long long u64;

// ---------------- f32x2 packed helpers --------------------------------------
__device__ __forceinline__ u64 ffma2(u64 a, u64 b, u64 c) {
    u64 d;
    asm("fma.rn.f32x2 %0, %1, %2, %3;" : "=l"(d) : "l"(a), "l"(b), "l"(c));
    return d;
}
__device__ __forceinline__ u64 addf2(u64 a, u64 b) {
    u64 d;
    asm("add.rn.f32x2 %0, %1, %2;" : "=l"(d) : "l"(a), "l"(b));
    return d;
}
__device__ __forceinline__ u64 packf2(float lo, float hi) {
    u64 v;
    asm("mov.b64 %0, {%1, %2};" : "=l"(v) : "f"(lo), "f"(hi));
    return v;
}
__device__ __forceinline__ float hsum2(u64 v) {
    float lo, hi;
    asm("mov.b64 {%0, %1}, %2;" : "=f"(lo), "=f"(hi) : "l"(v));
    return lo + hi;
}
// fast tanh (MUFU.TANH, abs err ~5e-4 max; errors random-sign, damped by f<1)
__device__ __forceinline__ float tanh_fast(float x) {
    float y;
    asm("tanh.approx.f32 %0, %1;" : "=f"(y) : "f"(x));
    return y;
}

// xp slot for gate-row j (PyTorch order i,f,g,o) -> per-unit slots [i, g, f, o]
__device__ __forceinline__ int xp_slot(int j) {
    int u = j % 100, gg = j / 100;
    int off = (gg == 0) ? 0 : (gg == 2) ? 1 : (gg == 1) ? 2 : 3;
    return 4 * u + off;
}
// prescale: sigmoid rows (i,f,o) x0.5 for sig(x)=0.5+0.5*tanh(x/2); g rows x1
__device__ __forceinline__ float row_scale(int j) {
    return (j >= 200 && j < 300) ? 1.0f : 0.5f;
}

// ---------------- kernel 0: prep --------------------------------------------
__global__ void prep_kernel(const float* __restrict__ Wih0,
                            const float* __restrict__ Winp,
                            const float* __restrict__ binp,
                            const float* __restrict__ bih0,
                            const float* __restrict__ bhh0,
                            const float* __restrict__ Wout) {
    int tid = blockIdx.x * blockDim.x + threadIdx.x;
    if (tid < 400 * DIN) {                              // WcT[k][j], row-scaled
        int j = tid / DIN, k = tid % DIN;
        float s = 0.f;
        for (int m = 0; m < HID; m++)
            s = fmaf(Wih0[j * HID + m], Winp[m * DIN + k], s);
        g_WcT[k * 400 + j] = s * row_scale(j);
    } else if (tid < 400 * DIN + 400) {                 // bc[j], row-scaled
        int j = tid - 400 * DIN;
        float s = bih0[j] + bhh0[j];
        for (int m = 0; m < HID; m++)
            s = fmaf(Wih0[j * HID + m], binp[m], s);
        g_bc[j] = s * row_scale(j);
    } else if (tid < 400 * DIN + 400 + DIN * HID) {     // WoutT[k][d]
        int q = tid - (400 * DIN + 400);
        int d = q / HID, k = q % HID;
        g_WoutT[k * DIN + d] = Wout[d * HID + k];
    } else if (tid < 400 * DIN + 400 + DIN * HID + NCHUNK + NXTILE + 1) {
        int q = tid - (400 * DIN + 400 + DIN * HID);
        if (q < NCHUNK)               g_flag1[q] = 0;
        else if (q < NCHUNK + NXTILE) g_flag0[q - NCHUNK] = 0;
        else                          g_prog0 = 0;
    }
}

// ---------------- xp0 producer (2 gate rows / thread) ----------------------
__device__ void xp0_producer(int pb, const float* __restrict__ inputs) {
    __shared__ __align__(16) float inpT[DIN * XTILE];   // [k][t], 38.4 KB
    const int j  = threadIdx.x;                         // rows j and j+200
    const int r0 = j, r1 = j + 200;
    const int s0 = xp_slot(r0), s1 = xp_slot(r1);
    const float b0 = g_bc[r0], b1 = g_bc[r1];           // already row-scaled

    for (int ti = pb; ti < NXTILE; ti += NXPB) {
        const int t0 = ti * XTILE;
        for (int idx = j; idx < XTILE * DIN; idx += THR) {
            int t = idx / DIN, k = idx % DIN;
            inpT[k * XTILE + t] = inputs[(t0 + t) * DIN + k];
        }
        __syncthreads();

        u64 acc0[16], acc1[16];
        #pragma unroll
        for (int tp = 0; tp < 16; tp++) {
            acc0[tp] = packf2(b0, b0);
            acc1[tp] = packf2(b1, b1);
        }
        #pragma unroll 2
        for (int k = 0; k < DIN; k++) {
            float w0 = g_WcT[k * 400 + r0];
            float w1 = g_WcT[k * 400 + r1];
            u64 w02 = packf2(w0, w0), w12 = packf2(w1, w1);
            const u64* row2 = (const u64*)(inpT + k * XTILE);
            #pragma unroll
            for (int tp = 0; tp < 16; tp++) {
                u64 hv = row2[tp];
                acc0[tp] = ffma2(w02, hv, acc0[tp]);
                acc1[tp] = ffma2(w12, hv, acc1[tp]);
            }
        }
        #pragma unroll
        for (int tp = 0; tp < 16; tp++) {
            float a, b;
            asm("mov.b64 {%0, %1}, %2;" : "=f"(a), "=f"(b) : "l"(acc0[tp]));
            g_xp0[(t0 + 2 * tp + 0) * XROW + s0] = a;
            g_xp0[(t0 + 2 * tp + 1) * XROW + s0] = b;
            asm("mov.b64 {%0, %1}, %2;" : "=f"(a), "=f"(b) : "l"(acc1[tp]));
            g_xp0[(t0 + 2 * tp + 0) * XROW + s1] = a;
            g_xp0[(t0 + 2 * tp + 1) * XROW + s1] = b;
        }
        __threadfence();
        __syncthreads();                                // also protects inpT reuse
        if (j == 0) g_flag0[ti] = 1;
    }
}

// ---------------- layer scan (blocks 0 and 1) — o-chain pipelined tail ------
// tid = 2u + p. Lane pair = one hidden unit; p selects the k-half.
// SOFTWARE-PIPELINED STEP: loop A computes i,f,g chains; their reduction,
// shfl, activations, c-update and tanh(c) are ISSUED before loop B (o chain,
// h reloaded from smem), so the act work overlaps the remaining FMA drain.
// Post-drain serial path is only: reduce-o -> shfl -> tanh -> h -> STS -> bar.
// xp folded into accumulator INIT. Both lanes compute c/h redundantly
// (commutative sums -> bit-exact, zero divergence). One barrier per step.
template <int L>
__device__ void layer_scan(const float* __restrict__ Whh,
                           const float* __restrict__ xp_src,
                           float* __restrict__ h_dst,
                           float* __restrict__ out) {
    __shared__ __align__(16) float hs[2][112];          // double-buffered h
    const int tid = threadIdx.x;
    const int u   = tid >> 1;
    const int p   = tid & 1;
    const int kb  = p * 50;
    const unsigned mask = (tid < 192) ? 0xFFFFFFFFu : 0x000000FFu;

    u64 wI[25], wG[25], wF[25], wO[25];                 // 100 u64 (200 regs)
    {
        const float2* rI = (const float2*)(Whh + u * HID + kb);
        const float2* rG = (const float2*)(Whh + (200 + u) * HID + kb);
        const float2* rF = (const float2*)(Whh + (100 + u) * HID + kb);
        const float2* rO = (const float2*)(Whh + (300 + u) * HID + kb);
        #pragma unroll
        for (int k = 0; k < 25; k++) {
            float2 a = rI[k], b = rG[k], c2 = rF[k], d = rO[k];
            wI[k] = packf2(0.5f * a.x, 0.5f * a.y);     // sigmoid half-scale
            wG[k] = packf2(b.x, b.y);                   // tanh direct
            wF[k] = packf2(0.5f * c2.x, 0.5f * c2.y);
            wO[k] = packf2(0.5f * d.x, 0.5f * d.y);
        }
    }
    if (tid < HID) hs[0][tid] = 0.f;
    __syncthreads();

    float c = 0.f, hcur = 0.f;
    const float2* xp_p = ((const float2*)xp_src) + tid; // p0:{i,g}, p1:{f,o}
    float2 xc = make_float2(0.f, 0.f), xn = xc;

    for (int cb = 0; cb < TT / 32; cb++) {
        if (tid == 0) {                                 // readiness wait, hoisted
            if (L == 0) {
                int f1 = (cb + 1 < NXTILE) ? cb + 1 : NXTILE - 1;
                while (!(g_flag0[cb] && g_flag0[f1])) __nanosleep(64);
            } else {
                int c0 = cb >> 1;
                int c1 = (c0 + 1 < NCHUNK) ? c0 + 1 : NCHUNK - 1;
                while (!(g_flag1[c0] && g_flag1[c1])) __nanosleep(64);
            }
            __threadfence();
        }
        __syncthreads();
        if (cb == 0) { xc = xp_p[0]; xn = xp_p[XROW2]; }

        for (int tt = 0; tt < 32; tt++) {
            const int t = cb * 32 + tt;
            const u64* hv = (const u64*)(hs[t & 1] + kb);

            // xp folded into accumulator init (lane owns 2 gate slots)
            const float xiv = (p == 0) ? xc.x : 0.f;
            const float xgv = (p == 0) ? xc.y : 0.f;
            const float xfv = (p == 1) ? xc.x : 0.f;
            const float xov = (p == 1) ? xc.y : 0.f;

            // ---- loop A: i, f, g chains (75 FFMA2) ----
            u64 i0 = packf2(xiv, 0.f), i1 = 0ull;
            u64 f0 = packf2(xfv, 0.f), f1 = 0ull;
            u64 g0 = packf2(xgv, 0.f), g1 = 0ull;
            #pragma unroll
            for (int k = 0; k < 25; k++) {
                u64 hq = hv[k];
                if (k & 1) {
                    i1 = ffma2(wI[k], hq, i1);
                    f1 = ffma2(wF[k], hq, f1);
                    g1 = ffma2(wG[k], hq, g1);
                } else {
                    i0 = ffma2(wI[k], hq, i0);
                    f0 = ffma2(wF[k], hq, f0);
                    g0 = ffma2(wG[k], hq, g0);
                }
            }

            // ---- early tail: acts for i,f,g + c + tanh(c), overlaps loop B ----
            float Pi = hsum2(addf2(i0, i1));
            float Pf = hsum2(addf2(f0, f1));
            float Pg = hsum2(addf2(g0, g1));
            float Qi = __shfl_xor_sync(mask, Pi, 1);
            float Qf = __shfl_xor_sync(mask, Pf, 1);
            float Qg = __shfl_xor_sync(mask, Pg, 1);
            float a_i = fmaf(0.5f, tanh_fast(Pi + Qi), 0.5f);   // sig(i)
            float a_f = fmaf(0.5f, tanh_fast(Pf + Qf), 0.5f);   // sig(f)
            float a_g = tanh_fast(Pg + Qg);                     // tanh(g)
            c = fmaf(a_f, c, a_i * a_g);                // redundant in both lanes
            float thc = tanh_fast(c);                   // issued early, used late

            float2 xf2 = xp_p[2 * XROW2];               // prefetch t+2 (padded)

            // ---- loop B: o chain (25 FFMA2, h reloaded from smem) ----
            u64 o0 = packf2(xov, 0.f), o1 = 0ull;
            #pragma unroll
            for (int k = 0; k < 25; k++) {
                u64 hq = hv[k];
                if (k & 1) o1 = ffma2(wO[k], hq, o1);
                else       o0 = ffma2(wO[k], hq, o0);
            }

            // ---- final tail: only o's act on the post-drain serial path ----
            float Po = hsum2(addf2(o0, o1));
            float Qo = __shfl_xor_sync(mask, Po, 1);
            float a_o = fmaf(0.5f, tanh_fast(Po + Qo), 0.5f);   // sig(o)
            hcur = a_o * thc;

            if (p == 0) {
                hs[(t + 1) & 1][u] = hcur;
                h_dst[t * HID + u] = hcur;
            }
            __syncthreads();                            // single barrier per step

            xc = xn; xn = xf2; xp_p += XROW2;
        }

        if (L == 0) {                                   // publish per 32 steps
            __threadfence();
            __syncthreads();
            if (tid == 0) g_prog0 = (cb + 1) * 32;
        }
    }

    if (p == 0) {                                       // h_n / c_n tails
        out[TT * DIN + L * HID + u]           = hcur;
        out[TT * DIN + 2 * HID + L * HID + u] = c;
    }
}

// ---------------- chaser: xp1 = h0 @ Wih1^T + b (blocks 2..9) --------------
__device__ void chaser(int ci,
                       const float* __restrict__ Wih1,
                       const float* __restrict__ bih1,
                       const float* __restrict__ bhh1) {
    __shared__ __align__(16) float h0s[CH * HID];       // 25.6 KB
    const int j  = threadIdx.x;                         // rows 2j, 2j+1
    const int r0 = 2 * j, r1 = 2 * j + 1;
    const float wsA = row_scale(r0), wsB = row_scale(r1);

    u64 wA[50], wB[50];
    #pragma unroll
    for (int q = 0; q < 50; q++) {
        wA[q] = packf2(wsA * Wih1[r0 * HID + 2 * q], wsA * Wih1[r0 * HID + 2 * q + 1]);
        wB[q] = packf2(wsB * Wih1[r1 * HID + 2 * q], wsB * Wih1[r1 * HID + 2 * q + 1]);
    }
    const float bA = wsA * (bih1[r0] + bhh1[r0]);
    const float bB = wsB * (bih1[r1] + bhh1[r1]);
    const int sA = xp_slot(r0), sB = xp_slot(r1);

    for (int cidx = ci; cidx < NCHUNK; cidx += NCHASE) {
        const int t0 = cidx * CH;
        if (j == 0) {
            while (g_prog0 < t0 + CH) __nanosleep(128);
            __threadfence();
        }
        __syncthreads();
        {
            const float4* src = (const float4*)(g_h0 + t0 * HID);
            float4*       dst = (float4*)h0s;
            for (int idx = j; idx < CH * HID / 4; idx += THR)
                dst[idx] = src[idx];
        }
        __syncthreads();

        for (int t = 0; t < CH; t++) {
            const u64* hv = (const u64*)(h0s + t * HID);
            u64 aA = 0ull, aB = 0ull;
            #pragma unroll 10
            for (int q = 0; q < 50; q++) {
                u64 hq = hv[q];
                aA = ffma2(wA[q], hq, aA);
                aB = ffma2(wB[q], hq, aB);
            }
            g_xp1[(t0 + t) * XROW + sA] = bA + hsum2(aA);
            g_xp1[(t0 + t) * XROW + sB] = bB + hsum2(aB);
        }
        __threadfence();
        __syncthreads();
        if (j == 0) g_flag1[cidx] = 1;
    }
}

// ---------------- persistent kernel -----------------------------------------
__global__ __launch_bounds__(THR, 1)
void scan_kernel(const float* __restrict__ inputs,
                 const float* __restrict__ Whh0,
                 const float* __restrict__ Wih1,
                 const float* __restrict__ Whh1,
                 const float* __restrict__ bih1,
                 const float* __restrict__ bhh1,
                 float* __restrict__ out) {
    if (blockIdx.x == 0)       layer_scan<0>(Whh0, g_xp0, g_h0, out);
    else if (blockIdx.x == 1)  layer_scan<1>(Whh1, g_xp1, g_h1, out);
    else if (blockIdx.x < 2 + NCHASE) chaser(blockIdx.x - 2, Wih1, bih1, bhh1);
    else                       xp0_producer(blockIdx.x - 2 - NCHASE, inputs);
}

// ---------------- kernel 2: outputs = h1_seq @ W_out^T + b_out -------------
__global__ __launch_bounds__(320) void out_gemm(const float* __restrict__ bout,
                                                float* __restrict__ out) {
    __shared__ __align__(16) float h1s[OT * HID];
    const int t0 = blockIdx.x * OT;
    const int d  = threadIdx.x;

    {
        const float4* src = (const float4*)(g_h1 + t0 * HID);
        float4*       dst = (float4*)h1s;
        for (int idx = threadIdx.x; idx < OT * HID / 4; idx += 320)
            dst[idx] = src[idx];
    }
    __syncthreads();

    if (d < DIN) {
        u64 w[50];
        #pragma unroll
        for (int kk = 0; kk < 50; kk++)
            w[kk] = packf2(g_WoutT[(2 * kk) * DIN + d], g_WoutT[(2 * kk + 1) * DIN + d]);
        const float bd = bout[d];
        for (int t = 0; t < OT; t++) {
            const u64* hv = (const u64*)(h1s + t * HID);
            u64 a0 = 0ull, a1 = 0ull;
            #pragma unroll 5
            for (int k = 0; k < 25; k++) {
                a0 = ffma2(w[2 * k + 0], hv[2 * k + 0], a0);
                a1 = ffma2(w[2 * k + 1], hv[2 * k + 1], a1);
            }
            out[(t0 + t) * DIN + d] = bd + hsum2(a0) + hsum2(a1);
        }
    }
}

// ---------------- launch ----------------------------------------------------
extern "C" void kernel_launch(void* const* d_in, const int* in_sizes, int n_in,
                              void* d_out, int out_size) {
    (void)in_sizes; (void)n_in; (void)out_size;
    const float* inputs = (const float*)d_in[0];
    const float* W_inp  = (const float*)d_in[1];
    const float* b_inp  = (const float*)d_in[2];
    const float* Wih0   = (const float*)d_in[3];
    const float* Whh0   = (const float*)d_in[4];
    const float* bih0   = (const float*)d_in[5];
    const float* bhh0   = (const float*)d_in[6];
    const float* Wih1   = (const float*)d_in[7];
    const float* Whh1   = (const float*)d_in[8];
    const float* bih1   = (const float*)d_in[9];
    const float* bhh1   = (const float*)d_in[10];
    const float* Wout   = (const float*)d_in[11];
    const float* bout   = (const float*)d_in[12];
    float* out = (float*)d_out;

    int prep_items = 400 * DIN + 400 + DIN * HID + NCHUNK + NXTILE + 1;
    prep_kernel<<<(prep_items + 255) / 256, 256>>>(Wih0, W_inp, b_inp, bih0, bhh0, Wout);
    scan_kernel<<<2 + NCHASE + NXPB, THR>>>(inputs, Whh0, Wih1, Whh1, bih1, bhh1, out);
    out_gemm<<<TT / OT, 320>>>(bout, out);
}

// round 16
// speedup vs baseline: 1.8026x; 1.8026x over previous
#include <cuda_runtime.h>

#define TT     32768
#define HID    100
#define DIN    300
#define THR    200                 // uniform block size
#define XROW   400                 // xp row stride (floats)
#define XROW2  200                 // xp row stride (float2)
#define XTILE  32                  // xp0 producer tile (timesteps)
#define NXTILE (TT / XTILE)        // 1024
#define NXPB   64                  // xp0 producer blocks
#define CH     64                  // chaser chunk (timesteps)
#define NCHUNK (TT / CH)           // 512
#define NCHASE 8
#define OT     16                  // out_gemm tile (timesteps)

// ---------------- scratch (static device allocations) ----------------------
// xp rows pre-scaled: i,f,o rows x0.5 (sigmoid via 0.5+0.5*tanh(y)), g rows x1
__device__ float g_xp0[(TT + 2) * XROW];  // layer-0 input proj, [t][4u+{i,g,f,o}]
__device__ float g_xp1[(TT + 2) * XROW];  // layer-1 input proj, same layout
__device__ float g_h0[TT * HID];          // layer-0 hidden sequence [t][u]
__device__ float g_h1[TT * HID];          // layer-1 hidden sequence [t][u]
__device__ float g_WcT[DIN * 400];        // fused (W_ih_l0 @ W_inp)^T [k][j], row-scaled
__device__ float g_bc[400];               // fused layer-0 gate bias, row-scaled
__device__ float g_WoutT[HID * DIN];      // W_out transposed [k][d]
__device__ volatile int g_prog0;          // layer-0 progress (steps completed)
__device__ volatile int g_flag0[NXTILE];  // xp0 tile-ready flags
__device__ volatile int g_flag1[NCHUNK];  // xp1 chunk-ready flags

typedef unsigned long long u64;

// ---------------- f32x2 packed helpers --------------------------------------
__device__ __forceinline__ u64 ffma2(u64 a, u64 b, u64 c) {
    u64 d;
    asm("fma.rn.f32x2 %0, %1, %2, %3;" : "=l"(d) : "l"(a), "l"(b), "l"(c));
    return d;
}
__device__ __forceinline__ u64 addf2(u64 a, u64 b) {
    u64 d;
    asm("add.rn.f32x2 %0, %1, %2;" : "=l"(d) : "l"(a), "l"(b));
    return d;
}
__device__ __forceinline__ u64 packf2(float lo, float hi) {
    u64 v;
    asm("mov.b64 %0, {%1, %2};" : "=l"(v) : "f"(lo), "f"(hi));
    return v;
}
__device__ __forceinline__ float hsum2(u64 v) {
    float lo, hi;
    asm("mov.b64 {%0, %1}, %2;" : "=f"(lo), "=f"(hi) : "l"(v));
    return lo + hi;
}
// fast tanh (MUFU.TANH, abs err ~5e-4 max; errors random-sign, damped by f<1)
__device__ __forceinline__ float tanh_fast(float x) {
    float y;
    asm("tanh.approx.f32 %0, %1;" : "=f"(y) : "f"(x));
    return y;
}

// xp slot for gate-row j (PyTorch order i,f,g,o) -> per-unit slots [i, g, f, o]
__device__ __forceinline__ int xp_slot(int j) {
    int u = j % 100, gg = j / 100;
    int off = (gg == 0) ? 0 : (gg == 2) ? 1 : (gg == 1) ? 2 : 3;
    return 4 * u + off;
}
// prescale: sigmoid rows (i,f,o) x0.5 for sig(x)=0.5+0.5*tanh(x/2); g rows x1
__device__ __forceinline__ float row_scale(int j) {
    return (j >= 200 && j < 300) ? 1.0f : 0.5f;
}

// ---------------- kernel 0: prep --------------------------------------------
__global__ void prep_kernel(const float* __restrict__ Wih0,
                            const float* __restrict__ Winp,
                            const float* __restrict__ binp,
                            const float* __restrict__ bih0,
                            const float* __restrict__ bhh0,
                            const float* __restrict__ Wout) {
    int tid = blockIdx.x * blockDim.x + threadIdx.x;
    if (tid < 400 * DIN) {                              // WcT[k][j], row-scaled
        int j = tid / DIN, k = tid % DIN;
        float s = 0.f;
        for (int m = 0; m < HID; m++)
            s = fmaf(Wih0[j * HID + m], Winp[m * DIN + k], s);
        g_WcT[k * 400 + j] = s * row_scale(j);
    } else if (tid < 400 * DIN + 400) {                 // bc[j], row-scaled
        int j = tid - 400 * DIN;
        float s = bih0[j] + bhh0[j];
        for (int m = 0; m < HID; m++)
            s = fmaf(Wih0[j * HID + m], binp[m], s);
        g_bc[j] = s * row_scale(j);
    } else if (tid < 400 * DIN + 400 + DIN * HID) {     // WoutT[k][d]
        int q = tid - (400 * DIN + 400);
        int d = q / HID, k = q % HID;
        g_WoutT[k * DIN + d] = Wout[d * HID + k];
    } else if (tid < 400 * DIN + 400 + DIN * HID + NCHUNK + NXTILE + 1) {
        int q = tid - (400 * DIN + 400 + DIN * HID);
        if (q < NCHUNK)               g_flag1[q] = 0;
        else if (q < NCHUNK + NXTILE) g_flag0[q - NCHUNK] = 0;
        else                          g_prog0 = 0;
    }
}

// ---------------- xp0 producer (2 gate rows / thread) ----------------------
__device__ void xp0_producer(int pb, const float* __restrict__ inputs) {
    __shared__ __align__(16) float inpT[DIN * XTILE];   // [k][t], 38.4 KB
    const int j  = threadIdx.x;                         // rows j and j+200
    const int r0 = j, r1 = j + 200;
    const int s0 = xp_slot(r0), s1 = xp_slot(r1);
    const float b0 = g_bc[r0], b1 = g_bc[r1];           // already row-scaled

    for (int ti = pb; ti < NXTILE; ti += NXPB) {
        const int t0 = ti * XTILE;
        for (int idx = j; idx < XTILE * DIN; idx += THR) {
            int t = idx / DIN, k = idx % DIN;
            inpT[k * XTILE + t] = inputs[(t0 + t) * DIN + k];
        }
        __syncthreads();

        u64 acc0[16], acc1[16];
        #pragma unroll
        for (int tp = 0; tp < 16; tp++) {
            acc0[tp] = packf2(b0, b0);
            acc1[tp] = packf2(b1, b1);
        }
        #pragma unroll 2
        for (int k = 0; k < DIN; k++) {
            float w0 = g_WcT[k * 400 + r0];
            float w1 = g_WcT[k * 400 + r1];
            u64 w02 = packf2(w0, w0), w12 = packf2(w1, w1);
            const u64* row2 = (const u64*)(inpT + k * XTILE);
            #pragma unroll
            for (int tp = 0; tp < 16; tp++) {
                u64 hv = row2[tp];
                acc0[tp] = ffma2(w02, hv, acc0[tp]);
                acc1[tp] = ffma2(w12, hv, acc1[tp]);
            }
        }
        #pragma unroll
        for (int tp = 0; tp < 16; tp++) {
            float a, b;
            asm("mov.b64 {%0, %1}, %2;" : "=f"(a), "=f"(b) : "l"(acc0[tp]));
            g_xp0[(t0 + 2 * tp + 0) * XROW + s0] = a;
            g_xp0[(t0 + 2 * tp + 1) * XROW + s0] = b;
            asm("mov.b64 {%0, %1}, %2;" : "=f"(a), "=f"(b) : "l"(acc1[tp]));
            g_xp0[(t0 + 2 * tp + 0) * XROW + s1] = a;
            g_xp0[(t0 + 2 * tp + 1) * XROW + s1] = b;
        }
        __threadfence();
        __syncthreads();                                // also protects inpT reuse
        if (j == 0) g_flag0[ti] = 1;
    }
}

// ---------------- layer scan (blocks 0 and 1) — R13 structure ---------------
// tid = 2u + p. Lane pair = one hidden unit; p selects the k-half.
// Each thread: 4 rows (i,g,f,o) x 25 k-pairs; i/f/o rows prescaled x0.5.
// xp folded into local partials BEFORE the exchange; 4x shfl_xor exchanges
// all row partials; BOTH lanes compute acts/c/h redundantly (bit-exact,
// FADD commutative) -> zero divergence. ALL activations via MUFU.TANH:
// sig = 0.5 + 0.5*tanh(y), tanh(g) direct. Single __syncthreads per step.
// xp[t+2] prefetch hoisted ABOVE the FMA loop (issues early, drains under it).
template <int L>
__device__ void layer_scan(const float* __restrict__ Whh,
                           const float* __restrict__ xp_src,
                           float* __restrict__ h_dst,
                           float* __restrict__ out) {
    __shared__ __align__(16) float hs[2][112];          // double-buffered h
    const int tid = threadIdx.x;
    const int u   = tid >> 1;
    const int p   = tid & 1;
    const int kb  = p * 50;
    const unsigned mask = (tid < 192) ? 0xFFFFFFFFu : 0x000000FFu;

    u64 wI[25], wG[25], wF[25], wO[25];                 // 100 u64
    {
        const float2* rI = (const float2*)(Whh + u * HID + kb);
        const float2* rG = (const float2*)(Whh + (200 + u) * HID + kb);
        const float2* rF = (const float2*)(Whh + (100 + u) * HID + kb);
        const float2* rO = (const float2*)(Whh + (300 + u) * HID + kb);
        #pragma unroll
        for (int k = 0; k < 25; k++) {
            float2 a = rI[k], b = rG[k], c2 = rF[k], d = rO[k];
            wI[k] = packf2(0.5f * a.x, 0.5f * a.y);     // sigmoid half-scale
            wG[k] = packf2(b.x, b.y);                   // tanh direct
            wF[k] = packf2(0.5f * c2.x, 0.5f * c2.y);
            wO[k] = packf2(0.5f * d.x, 0.5f * d.y);
        }
    }
    if (tid < HID) hs[0][tid] = 0.f;
    __syncthreads();

    float c = 0.f, hcur = 0.f;
    const float2* xp_p = ((const float2*)xp_src) + tid; // p0:{i,g}, p1:{f,o}
    float2 xc = make_float2(0.f, 0.f), xn = xc;

    for (int cb = 0; cb < TT / 32; cb++) {
        if (tid == 0) {                                 // readiness wait, hoisted
            if (L == 0) {
                int f1 = (cb + 1 < NXTILE) ? cb + 1 : NXTILE - 1;
                while (!(g_flag0[cb] && g_flag0[f1])) __nanosleep(64);
            } else {
                int c0 = cb >> 1;
                int c1 = (c0 + 1 < NCHUNK) ? c0 + 1 : NCHUNK - 1;
                while (!(g_flag1[c0] && g_flag1[c1])) __nanosleep(64);
            }
            __threadfence();
        }
        __syncthreads();
        if (cb == 0) { xc = xp_p[0]; xn = xp_p[XROW2]; }

        for (int tt = 0; tt < 32; tt++) {
            const int t = cb * 32 + tt;
            const u64* hv = (const u64*)(hs[t & 1] + kb);

            float2 xf = xp_p[2 * XROW2];                // prefetch t+2, issued early

            u64 i0 = 0ull, i1 = 0ull, g0 = 0ull, g1 = 0ull;
            u64 f0 = 0ull, f1 = 0ull, o0 = 0ull, o1 = 0ull;
            #pragma unroll
            for (int k = 0; k < 25; k++) {
                u64 hq = hv[k];
                if (k & 1) {
                    i1 = ffma2(wI[k], hq, i1);
                    g1 = ffma2(wG[k], hq, g1);
                    f1 = ffma2(wF[k], hq, f1);
                    o1 = ffma2(wO[k], hq, o1);
                } else {
                    i0 = ffma2(wI[k], hq, i0);
                    g0 = ffma2(wG[k], hq, g0);
                    f0 = ffma2(wF[k], hq, f0);
                    o0 = ffma2(wO[k], hq, o0);
                }
            }

            float Pi = hsum2(addf2(i0, i1));
            float Pg = hsum2(addf2(g0, g1));
            float Pf = hsum2(addf2(f0, f1));
            float Po = hsum2(addf2(o0, o1));
            if (p == 0) { Pi += xc.x; Pg += xc.y; }     // fold xp pre-exchange
            else        { Pf += xc.x; Po += xc.y; }

            float Qi = __shfl_xor_sync(mask, Pi, 1);
            float Qg = __shfl_xor_sync(mask, Pg, 1);
            float Qf = __shfl_xor_sync(mask, Pf, 1);
            float Qo = __shfl_xor_sync(mask, Po, 1);

            // identical on both lanes (commutative adds) — zero divergence
            float a_i = fmaf(0.5f, tanh_fast(Pi + Qi), 0.5f);  // sig(i)
            float a_g = tanh_fast(Pg + Qg);                    // tanh(g)
            float a_f = fmaf(0.5f, tanh_fast(Pf + Qf), 0.5f);  // sig(f)
            float a_o = fmaf(0.5f, tanh_fast(Po + Qo), 0.5f);  // sig(o)

            c = fmaf(a_f, c, a_i * a_g);                // redundant in both lanes
            hcur = a_o * tanh_fast(c);

            if (p == 0) {
                hs[(t + 1) & 1][u] = hcur;
                h_dst[t * HID + u] = hcur;
            }
            __syncthreads();                            // single barrier per step

            xc = xn; xn = xf; xp_p += XROW2;
        }

        if (L == 0) {                                   // publish per 32 steps
            __threadfence();
            __syncthreads();
            if (tid == 0) g_prog0 = (cb + 1) * 32;
        }
    }

    if (p == 0) {                                       // h_n / c_n tails
        out[TT * DIN + L * HID + u]           = hcur;
        out[TT * DIN + 2 * HID + L * HID + u] = c;
    }
}

// ---------------- chaser: xp1 = h0 @ Wih1^T + b (blocks 2..9) --------------
__device__ void chaser(int ci,
                       const float* __restrict__ Wih1,
                       const float* __restrict__ bih1,
                       const float* __restrict__ bhh1) {
    __shared__ __align__(16) float h0s[CH * HID];       // 25.6 KB
    const int j  = threadIdx.x;                         // rows 2j, 2j+1
    const int r0 = 2 * j, r1 = 2 * j + 1;
    const float wsA = row_scale(r0), wsB = row_scale(r1);

    u64 wA[50], wB[50];
    #pragma unroll
    for (int q = 0; q < 50; q++) {
        wA[q] = packf2(wsA * Wih1[r0 * HID + 2 * q], wsA * Wih1[r0 * HID + 2 * q + 1]);
        wB[q] = packf2(wsB * Wih1[r1 * HID + 2 * q], wsB * Wih1[r1 * HID + 2 * q + 1]);
    }
    const float bA = wsA * (bih1[r0] + bhh1[r0]);
    const float bB = wsB * (bih1[r1] + bhh1[r1]);
    const int sA = xp_slot(r0), sB = xp_slot(r1);

    for (int cidx = ci; cidx < NCHUNK; cidx += NCHASE) {
        const int t0 = cidx * CH;
        if (j == 0) {
            while (g_prog0 < t0 + CH) __nanosleep(128);
            __threadfence();
        }
        __syncthreads();
        {
            const float4* src = (const float4*)(g_h0 + t0 * HID);
            float4*       dst = (float4*)h0s;
            for (int idx = j; idx < CH * HID / 4; idx += THR)
                dst[idx] = src[idx];
        }
        __syncthreads();

        for (int t = 0; t < CH; t++) {
            const u64* hv = (const u64*)(h0s + t * HID);
            u64 aA = 0ull, aB = 0ull;
            #pragma unroll 10
            for (int q = 0; q < 50; q++) {
                u64 hq = hv[q];
                aA = ffma2(wA[q], hq, aA);
                aB = ffma2(wB[q], hq, aB);
            }
            g_xp1[(t0 + t) * XROW + sA] = bA + hsum2(aA);
            g_xp1[(t0 + t) * XROW + sB] = bB + hsum2(aB);
        }
        __threadfence();
        __syncthreads();
        if (j == 0) g_flag1[cidx] = 1;
    }
}

// ---------------- persistent kernel -----------------------------------------
__global__ __launch_bounds__(THR, 1)
void scan_kernel(const float* __restrict__ inputs,
                 const float* __restrict__ Whh0,
                 const float* __restrict__ Wih1,
                 const float* __restrict__ Whh1,
                 const float* __restrict__ bih1,
                 const float* __restrict__ bhh1,
                 float* __restrict__ out) {
    if (blockIdx.x == 0)       layer_scan<0>(Whh0, g_xp0, g_h0, out);
    else if (blockIdx.x == 1)  layer_scan<1>(Whh1, g_xp1, g_h1, out);
    else if (blockIdx.x < 2 + NCHASE) chaser(blockIdx.x - 2, Wih1, bih1, bhh1);
    else                       xp0_producer(blockIdx.x - 2 - NCHASE, inputs);
}

// ---------------- kernel 2: outputs = h1_seq @ W_out^T + b_out -------------
__global__ __launch_bounds__(320) void out_gemm(const float* __restrict__ bout,
                                                float* __restrict__ out) {
    __shared__ __align__(16) float h1s[OT * HID];
    const int t0 = blockIdx.x * OT;
    const int d  = threadIdx.x;

    {
        const float4* src = (const float4*)(g_h1 + t0 * HID);
        float4*       dst = (float4*)h1s;
        for (int idx = threadIdx.x; idx < OT * HID / 4; idx += 320)
            dst[idx] = src[idx];
    }
    __syncthreads();

    if (d < DIN) {
        u64 w[50];
        #pragma unroll
        for (int kk = 0; kk < 50; kk++)
            w[kk] = packf2(g_WoutT[(2 * kk) * DIN + d], g_WoutT[(2 * kk + 1) * DIN + d]);
        const float bd = bout[d];
        for (int t = 0; t < OT; t++) {
            const u64* hv = (const u64*)(h1s + t * HID);
            u64 a0 = 0ull, a1 = 0ull;
            #pragma unroll 5
            for (int k = 0; k < 25; k++) {
                a0 = ffma2(w[2 * k + 0], hv[2 * k + 0], a0);
                a1 = ffma2(w[2 * k + 1], hv[2 * k + 1], a1);
            }
            out[(t0 + t) * DIN + d] = bd + hsum2(a0) + hsum2(a1);
        }
    }
}

// ---------------- launch ----------------------------------------------------
extern "C" void kernel_launch(void* const* d_in, const int* in_sizes, int n_in,
                              void* d_out, int out_size) {
    (void)in_sizes; (void)n_in; (void)out_size;
    const float* inputs = (const float*)d_in[0];
    const float* W_inp  = (const float*)d_in[1];
    const float* b_inp  = (const float*)d_in[2];
    const float* Wih0   = (const float*)d_in[3];
    const float* Whh0   = (const float*)d_in[4];
    const float* bih0   = (const float*)d_in[5];
    const float* bhh0   = (const float*)d_in[6];
    const float* Wih1   = (const float*)d_in[7];
    const float* Whh1   = (const float*)d_in[8];
    const float* bih1   = (const float*)d_in[9];
    const float* bhh1   = (const float*)d_in[10];
    const float* Wout   = (const float*)d_in[11];
    const float* bout   = (const float*)d_in[12];
    float* out = (float*)d_out;

    int prep_items = 400 * DIN + 400 + DIN * HID + NCHUNK + NXTILE + 1;
    prep_kernel<<<(prep_items + 255) / 256, 256>>>(Wih0, W_inp, b_inp, bih0, bhh0, Wout);
    scan_kernel<<<2 + NCHASE + NXPB, THR>>>(inputs, Whh0, Wih1, Whh1, bih1, bhh1, out);
    out_gemm<<<TT / OT, 320>>>(bout, out);
}

// round 17
// speedup vs baseline: 1.9861x; 1.1018x over previous
#include <cuda_runtime.h>

#define TT     32768
#define HID    100
#define DIN    300
#define THR    200                 // uniform block size
#define XROW   400                 // xp row stride (floats)
#define XROW2  200                 // xp row stride (float2)
#define XTILE  32                  // xp0 producer tile (timesteps)
#define NXTILE (TT / XTILE)        // 1024
#define NXPB   64                  // xp0 producer blocks
#define CH     64                  // chaser chunk (timesteps)
#define NCHUNK (TT / CH)           // 512
#define NCHASE 8
#define OT     16                  // out_gemm tile (timesteps)

// ---------------- scratch (static device allocations) ----------------------
// xp rows pre-scaled: i,f,o rows x0.5 (sigmoid via 0.5+0.5*tanh(y)), g rows x1
__device__ float g_xp0[(TT + 2) * XROW];  // layer-0 input proj, [t][4u+{i,g,f,o}]
__device__ float g_xp1[(TT + 2) * XROW];  // layer-1 input proj, same layout
__device__ float g_h0[TT * HID];          // layer-0 hidden sequence [t][u]
__device__ float g_h1[TT * HID];          // layer-1 hidden sequence [t][u]
__device__ float g_WcT[DIN * 400];        // fused (W_ih_l0 @ W_inp)^T [k][j], row-scaled
__device__ float g_bc[400];               // fused layer-0 gate bias, row-scaled
__device__ float g_WoutT[HID * DIN];      // W_out transposed [k][d]
__device__ volatile int g_prog0;          // layer-0 progress (steps completed)
__device__ volatile int g_flag0[NXTILE];  // xp0 tile-ready flags
__device__ volatile int g_flag1[NCHUNK];  // xp1 chunk-ready flags

typedef unsigned long long u64;

// ---------------- f32x2 packed helpers --------------------------------------
__device__ __forceinline__ u64 ffma2(u64 a, u64 b, u64 c) {
    u64 d;
    asm("fma.rn.f32x2 %0, %1, %2, %3;" : "=l"(d) : "l"(a), "l"(b), "l"(c));
    return d;
}
__device__ __forceinline__ u64 addf2(u64 a, u64 b) {
    u64 d;
    asm("add.rn.f32x2 %0, %1, %2;" : "=l"(d) : "l"(a), "l"(b));
    return d;
}
__device__ __forceinline__ u64 packf2(float lo, float hi) {
    u64 v;
    asm("mov.b64 %0, {%1, %2};" : "=l"(v) : "f"(lo), "f"(hi));
    return v;
}
__device__ __forceinline__ float hsum2(u64 v) {
    float lo, hi;
    asm("mov.b64 {%0, %1}, %2;" : "=f"(lo), "=f"(hi) : "l"(v));
    return lo + hi;
}
// fast tanh (MUFU.TANH, abs err ~5e-4 max; errors random-sign, damped by f<1)
__device__ __forceinline__ float tanh_fast(float x) {
    float y;
    asm("tanh.approx.f32 %0, %1;" : "=f"(y) : "f"(x));
    return y;
}

// xp slot for gate-row j (PyTorch order i,f,g,o) -> per-unit slots [i, g, f, o]
__device__ __forceinline__ int xp_slot(int j) {
    int u = j % 100, gg = j / 100;
    int off = (gg == 0) ? 0 : (gg == 2) ? 1 : (gg == 1) ? 2 : 3;
    return 4 * u + off;
}
// prescale: sigmoid rows (i,f,o) x0.5 for sig(x)=0.5+0.5*tanh(x/2); g rows x1
__device__ __forceinline__ float row_scale(int j) {
    return (j >= 200 && j < 300) ? 1.0f : 0.5f;
}

// ---------------- kernel 0: prep --------------------------------------------
__global__ void prep_kernel(const float* __restrict__ Wih0,
                            const float* __restrict__ Winp,
                            const float* __restrict__ binp,
                            const float* __restrict__ bih0,
                            const float* __restrict__ bhh0,
                            const float* __restrict__ Wout) {
    int tid = blockIdx.x * blockDim.x + threadIdx.x;
    if (tid < 400 * DIN) {                              // WcT[k][j], row-scaled
        int j = tid / DIN, k = tid % DIN;
        float s = 0.f;
        for (int m = 0; m < HID; m++)
            s = fmaf(Wih0[j * HID + m], Winp[m * DIN + k], s);
        g_WcT[k * 400 + j] = s * row_scale(j);
    } else if (tid < 400 * DIN + 400) {                 // bc[j], row-scaled
        int j = tid - 400 * DIN;
        float s = bih0[j] + bhh0[j];
        for (int m = 0; m < HID; m++)
            s = fmaf(Wih0[j * HID + m], binp[m], s);
        g_bc[j] = s * row_scale(j);
    } else if (tid < 400 * DIN + 400 + DIN * HID) {     // WoutT[k][d]
        int q = tid - (400 * DIN + 400);
        int d = q / HID, k = q % HID;
        g_WoutT[k * DIN + d] = Wout[d * HID + k];
    } else if (tid < 400 * DIN + 400 + DIN * HID + NCHUNK + NXTILE + 1) {
        int q = tid - (400 * DIN + 400 + DIN * HID);
        if (q < NCHUNK)               g_flag1[q] = 0;
        else if (q < NCHUNK + NXTILE) g_flag0[q - NCHUNK] = 0;
        else                          g_prog0 = 0;
    }
}

// ---------------- xp0 producer (2 gate rows / thread) ----------------------
__device__ void xp0_producer(int pb, const float* __restrict__ inputs) {
    __shared__ __align__(16) float inpT[DIN * XTILE];   // [k][t], 38.4 KB
    const int j  = threadIdx.x;                         // rows j and j+200
    const int r0 = j, r1 = j + 200;
    const int s0 = xp_slot(r0), s1 = xp_slot(r1);
    const float b0 = g_bc[r0], b1 = g_bc[r1];           // already row-scaled

    for (int ti = pb; ti < NXTILE; ti += NXPB) {
        const int t0 = ti * XTILE;
        for (int idx = j; idx < XTILE * DIN; idx += THR) {
            int t = idx / DIN, k = idx % DIN;
            inpT[k * XTILE + t] = inputs[(t0 + t) * DIN + k];
        }
        __syncthreads();

        u64 acc0[16], acc1[16];
        #pragma unroll
        for (int tp = 0; tp < 16; tp++) {
            acc0[tp] = packf2(b0, b0);
            acc1[tp] = packf2(b1, b1);
        }
        #pragma unroll 2
        for (int k = 0; k < DIN; k++) {
            float w0 = g_WcT[k * 400 + r0];
            float w1 = g_WcT[k * 400 + r1];
            u64 w02 = packf2(w0, w0), w12 = packf2(w1, w1);
            const u64* row2 = (const u64*)(inpT + k * XTILE);
            #pragma unroll
            for (int tp = 0; tp < 16; tp++) {
                u64 hv = row2[tp];
                acc0[tp] = ffma2(w02, hv, acc0[tp]);
                acc1[tp] = ffma2(w12, hv, acc1[tp]);
            }
        }
        #pragma unroll
        for (int tp = 0; tp < 16; tp++) {
            float a, b;
            asm("mov.b64 {%0, %1}, %2;" : "=f"(a), "=f"(b) : "l"(acc0[tp]));
            g_xp0[(t0 + 2 * tp + 0) * XROW + s0] = a;
            g_xp0[(t0 + 2 * tp + 1) * XROW + s0] = b;
            asm("mov.b64 {%0, %1}, %2;" : "=f"(a), "=f"(b) : "l"(acc1[tp]));
            g_xp0[(t0 + 2 * tp + 0) * XROW + s1] = a;
            g_xp0[(t0 + 2 * tp + 1) * XROW + s1] = b;
        }
        __threadfence();
        __syncthreads();                                // also protects inpT reuse
        if (j == 0) g_flag0[ti] = 1;
    }
}

// ---------------- layer scan (blocks 0 and 1) — R15 + thin post-drain tail --
// tid = 2u + p. Lane pair = one hidden unit; p selects the k-half.
// Each thread: 4 rows (i,g,f,o) x 25 k-pairs; i/f/o rows prescaled x0.5.
// SINGLE accumulator chain per gate (no post-drain addf2; frees 8 regs);
// xp folded into the accumulator INIT (selects off-chain, xc known early).
// 4x shfl_xor exchanges all row partials; BOTH lanes compute acts/c/h
// redundantly (bit-exact, commutative) -> zero divergence. ALL activations
// via MUFU.TANH. Single __syncthreads per step; xp[t+2] prefetch hoisted.
template <int L>
__device__ void layer_scan(const float* __restrict__ Whh,
                           const float* __restrict__ xp_src,
                           float* __restrict__ h_dst,
                           float* __restrict__ out) {
    __shared__ __align__(16) float hs[2][112];          // double-buffered h
    const int tid = threadIdx.x;
    const int u   = tid >> 1;
    const int p   = tid & 1;
    const int kb  = p * 50;
    const unsigned mask = (tid < 192) ? 0xFFFFFFFFu : 0x000000FFu;

    u64 wI[25], wG[25], wF[25], wO[25];                 // 100 u64
    {
        const float2* rI = (const float2*)(Whh + u * HID + kb);
        const float2* rG = (const float2*)(Whh + (200 + u) * HID + kb);
        const float2* rF = (const float2*)(Whh + (100 + u) * HID + kb);
        const float2* rO = (const float2*)(Whh + (300 + u) * HID + kb);
        #pragma unroll
        for (int k = 0; k < 25; k++) {
            float2 a = rI[k], b = rG[k], c2 = rF[k], d = rO[k];
            wI[k] = packf2(0.5f * a.x, 0.5f * a.y);     // sigmoid half-scale
            wG[k] = packf2(b.x, b.y);                   // tanh direct
            wF[k] = packf2(0.5f * c2.x, 0.5f * c2.y);
            wO[k] = packf2(0.5f * d.x, 0.5f * d.y);
        }
    }
    if (tid < HID) hs[0][tid] = 0.f;
    __syncthreads();

    float c = 0.f, hcur = 0.f;
    const float2* xp_p = ((const float2*)xp_src) + tid; // p0:{i,g}, p1:{f,o}
    float2 xc = make_float2(0.f, 0.f), xn = xc;

    for (int cb = 0; cb < TT / 32; cb++) {
        if (tid == 0) {                                 // readiness wait, hoisted
            if (L == 0) {
                int f1 = (cb + 1 < NXTILE) ? cb + 1 : NXTILE - 1;
                while (!(g_flag0[cb] && g_flag0[f1])) __nanosleep(64);
            } else {
                int c0 = cb >> 1;
                int c1 = (c0 + 1 < NCHUNK) ? c0 + 1 : NCHUNK - 1;
                while (!(g_flag1[c0] && g_flag1[c1])) __nanosleep(64);
            }
            __threadfence();
        }
        __syncthreads();
        if (cb == 0) { xc = xp_p[0]; xn = xp_p[XROW2]; }

        for (int tt = 0; tt < 32; tt++) {
            const int t = cb * 32 + tt;
            const u64* hv = (const u64*)(hs[t & 1] + kb);

            float2 xf = xp_p[2 * XROW2];                // prefetch t+2, issued early

            // xp folded into accumulator init (branchless, off critical path)
            u64 ai = packf2((p == 0) ? xc.x : 0.f, 0.f);
            u64 ag = packf2((p == 0) ? xc.y : 0.f, 0.f);
            u64 af = packf2((p == 1) ? xc.x : 0.f, 0.f);
            u64 ao = packf2((p == 1) ? xc.y : 0.f, 0.f);

            #pragma unroll
            for (int k = 0; k < 25; k++) {
                u64 hq = hv[k];
                ai = ffma2(wI[k], hq, ai);
                ag = ffma2(wG[k], hq, ag);
                af = ffma2(wF[k], hq, af);
                ao = ffma2(wO[k], hq, ao);
            }

            float Pi = hsum2(ai);
            float Pg = hsum2(ag);
            float Pf = hsum2(af);
            float Po = hsum2(ao);

            float Qi = __shfl_xor_sync(mask, Pi, 1);
            float Qg = __shfl_xor_sync(mask, Pg, 1);
            float Qf = __shfl_xor_sync(mask, Pf, 1);
            float Qo = __shfl_xor_sync(mask, Po, 1);

            // identical on both lanes (commutative adds) — zero divergence
            float a_i = fmaf(0.5f, tanh_fast(Pi + Qi), 0.5f);  // sig(i)
            float a_g = tanh_fast(Pg + Qg);                    // tanh(g)
            float a_f = fmaf(0.5f, tanh_fast(Pf + Qf), 0.5f);  // sig(f)
            float a_o = fmaf(0.5f, tanh_fast(Po + Qo), 0.5f);  // sig(o)

            c = fmaf(a_f, c, a_i * a_g);                // redundant in both lanes
            hcur = a_o * tanh_fast(c);

            if (p == 0) {
                hs[(t + 1) & 1][u] = hcur;
                h_dst[t * HID + u] = hcur;
            }
            __syncthreads();                            // single barrier per step

            xc = xn; xn = xf; xp_p += XROW2;
        }

        if (L == 0) {                                   // publish per 32 steps
            __threadfence();
            __syncthreads();
            if (tid == 0) g_prog0 = (cb + 1) * 32;
        }
    }

    if (p == 0) {                                       // h_n / c_n tails
        out[TT * DIN + L * HID + u]           = hcur;
        out[TT * DIN + 2 * HID + L * HID + u] = c;
    }
}

// ---------------- chaser: xp1 = h0 @ Wih1^T + b (blocks 2..9) --------------
__device__ void chaser(int ci,
                       const float* __restrict__ Wih1,
                       const float* __restrict__ bih1,
                       const float* __restrict__ bhh1) {
    __shared__ __align__(16) float h0s[CH * HID];       // 25.6 KB
    const int j  = threadIdx.x;                         // rows 2j, 2j+1
    const int r0 = 2 * j, r1 = 2 * j + 1;
    const float wsA = row_scale(r0), wsB = row_scale(r1);

    u64 wA[50], wB[50];
    #pragma unroll
    for (int q = 0; q < 50; q++) {
        wA[q] = packf2(wsA * Wih1[r0 * HID + 2 * q], wsA * Wih1[r0 * HID + 2 * q + 1]);
        wB[q] = packf2(wsB * Wih1[r1 * HID + 2 * q], wsB * Wih1[r1 * HID + 2 * q + 1]);
    }
    const float bA = wsA * (bih1[r0] + bhh1[r0]);
    const float bB = wsB * (bih1[r1] + bhh1[r1]);
    const int sA = xp_slot(r0), sB = xp_slot(r1);

    for (int cidx = ci; cidx < NCHUNK; cidx += NCHASE) {
        const int t0 = cidx * CH;
        if (j == 0) {
            while (g_prog0 < t0 + CH) __nanosleep(128);
            __threadfence();
        }
        __syncthreads();
        {
            const float4* src = (const float4*)(g_h0 + t0 * HID);
            float4*       dst = (float4*)h0s;
            for (int idx = j; idx < CH * HID / 4; idx += THR)
                dst[idx] = src[idx];
        }
        __syncthreads();

        for (int t = 0; t < CH; t++) {
            const u64* hv = (const u64*)(h0s + t * HID);
            u64 aA = 0ull, aB = 0ull;
            #pragma unroll 10
            for (int q = 0; q < 50; q++) {
                u64 hq = hv[q];
                aA = ffma2(wA[q], hq, aA);
                aB = ffma2(wB[q], hq, aB);
            }
            g_xp1[(t0 + t) * XROW + sA] = bA + hsum2(aA);
            g_xp1[(t0 + t) * XROW + sB] = bB + hsum2(aB);
        }
        __threadfence();
        __syncthreads();
        if (j == 0) g_flag1[cidx] = 1;
    }
}

// ---------------- persistent kernel -----------------------------------------
__global__ __launch_bounds__(THR, 1)
void scan_kernel(const float* __restrict__ inputs,
                 const float* __restrict__ Whh0,
                 const float* __restrict__ Wih1,
                 const float* __restrict__ Whh1,
                 const float* __restrict__ bih1,
                 const float* __restrict__ bhh1,
                 float* __restrict__ out) {
    if (blockIdx.x == 0)       layer_scan<0>(Whh0, g_xp0, g_h0, out);
    else if (blockIdx.x == 1)  layer_scan<1>(Whh1, g_xp1, g_h1, out);
    else if (blockIdx.x < 2 + NCHASE) chaser(blockIdx.x - 2, Wih1, bih1, bhh1);
    else                       xp0_producer(blockIdx.x - 2 - NCHASE, inputs);
}

// ---------------- kernel 2: outputs = h1_seq @ W_out^T + b_out -------------
__global__ __launch_bounds__(320) void out_gemm(const float* __restrict__ bout,
                                                float* __restrict__ out) {
    __shared__ __align__(16) float h1s[OT * HID];
    const int t0 = blockIdx.x * OT;
    const int d  = threadIdx.x;

    {
        const float4* src = (const float4*)(g_h1 + t0 * HID);
        float4*       dst = (float4*)h1s;
        for (int idx = threadIdx.x; idx < OT * HID / 4; idx += 320)
            dst[idx] = src[idx];
    }
    __syncthreads();

    if (d < DIN) {
        u64 w[50];
        #pragma unroll
        for (int kk = 0; kk < 50; kk++)
            w[kk] = packf2(g_WoutT[(2 * kk) * DIN + d], g_WoutT[(2 * kk + 1) * DIN + d]);
        const float bd = bout[d];
        for (int t = 0; t < OT; t++) {
            const u64* hv = (const u64*)(h1s + t * HID);
            u64 a0 = 0ull, a1 = 0ull;
            #pragma unroll 5
            for (int k = 0; k < 25; k++) {
                a0 = ffma2(w[2 * k + 0], hv[2 * k + 0], a0);
                a1 = ffma2(w[2 * k + 1], hv[2 * k + 1], a1);
            }
            out[(t0 + t) * DIN + d] = bd + hsum2(a0) + hsum2(a1);
        }
    }
}

// ---------------- launch ----------------------------------------------------
extern "C" void kernel_launch(void* const* d_in, const int* in_sizes, int n_in,
                              void* d_out, int out_size) {
    (void)in_sizes; (void)n_in; (void)out_size;
    const float* inputs = (const float*)d_in[0];
    const float* W_inp  = (const float*)d_in[1];
    const float* b_inp  = (const float*)d_in[2];
    const float* Wih0   = (const float*)d_in[3];
    const float* Whh0   = (const float*)d_in[4];
    const float* bih0   = (const float*)d_in[5];
    const float* bhh0   = (const float*)d_in[6];
    const float* Wih1   = (const float*)d_in[7];
    const float* Whh1   = (const float*)d_in[8];
    const float* bih1   = (const float*)d_in[9];
    const float* bhh1   = (const float*)d_in[10];
    const float* Wout   = (const float*)d_in[11];
    const float* bout   = (const float*)d_in[12];
    float* out = (float*)d_out;

    int prep_items = 400 * DIN + 400 + DIN * HID + NCHUNK + NXTILE + 1;
    prep_kernel<<<(prep_items + 255) / 256, 256>>>(Wih0, W_inp, b_inp, bih0, bhh0, Wout);
    scan_kernel<<<2 + NCHASE + NXPB, THR>>>(inputs, Whh0, Wih1, Whh1, bih1, bhh1, out);
    out_gemm<<<TT / OT, 320>>>(bout, out);
}